// round 13
// baseline (speedup 1.0000x reference)
#include <cuda_runtime.h>
#include <cuda_bf16.h>
#include <cstdint>
#include <math_constants.h>

// Problem: T=16384 tokens (S=4096*B=4), H=2048, E=64, top_k=2
#define NTOK 16384
#define HDIM 2048
#define NEXP 64
#define BM   64               // tokens per CTA (2 CTAs/SM)
#define KC   64               // K elems per chunk (four k16 steps, one per warpgroup)
#define NCH  (HDIM / KC)      // 32 chunks
#define THREADS 256
#define TAU  1.5e-4f          // top-k ambiguity margin (>> split error ~1e-6)

// ---- 3-stage smem ring: X fp32 + Whi/Wlo bf16 per stage -------------------
#define XROWB   288                        // X row stride bytes (72 floats; 4r+t bank-injective)
#define WROWB   144                        // W row stride bytes (72 bf16)
#define STG_X   0
#define STG_WHI (BM * XROWB)               // 18432
#define STG_WLO (STG_WHI + NEXP * WROWB)   // 27648
#define STG_B   (STG_WLO + NEXP * WROWB)   // 36864 per stage
#define NSTG    3
#define SM_TOTAL (NSTG * STG_B)            // 110592 (x2 CTAs = 221184)

// W preconverted to bf16 hi/lo (512KB, device-global scratch)
__device__ __nv_bfloat16 g_whi[NEXP * HDIM];
__device__ __nv_bfloat16 g_wlo[NEXP * HDIM];
// ambiguous-token list for exact index refinement
__device__ int g_nflag;
__device__ int g_ftok[NTOK];

// ---------------- PTX helpers (base sm_100 / sm_80-era only) ---------------
__device__ __forceinline__ uint32_t smem_u32(const void* p) {
    uint32_t a;
    asm("{ .reg .u64 t; cvta.to.shared.u64 t, %1; cvt.u32.u64 %0, t; }" : "=r"(a) : "l"(p));
    return a;
}
__device__ __forceinline__ float2 lds64(uint32_t addr) {
    float2 v;
    asm volatile("ld.shared.v2.f32 {%0,%1}, [%2];" : "=f"(v.x), "=f"(v.y) : "r"(addr));
    return v;
}
__device__ __forceinline__ float4 lds128f(uint32_t addr) {
    float4 v;
    asm volatile("ld.shared.v4.f32 {%0,%1,%2,%3}, [%4];"
                 : "=f"(v.x), "=f"(v.y), "=f"(v.z), "=f"(v.w) : "r"(addr));
    return v;
}
__device__ __forceinline__ void sts128f(uint32_t addr, float x, float y, float z, float w) {
    asm volatile("st.shared.v4.f32 [%0], {%1,%2,%3,%4};"
                 :: "r"(addr), "f"(x), "f"(y), "f"(z), "f"(w) : "memory");
}
__device__ __forceinline__ void ldsm4(uint32_t& r0, uint32_t& r1, uint32_t& r2, uint32_t& r3,
                                      uint32_t addr) {
    asm volatile("ldmatrix.sync.aligned.m8n8.x4.shared.b16 {%0,%1,%2,%3}, [%4];"
                 : "=r"(r0), "=r"(r1), "=r"(r2), "=r"(r3) : "r"(addr));
}
__device__ __forceinline__ void mma16816(float* c, const uint32_t* a, const uint32_t* b) {
    asm volatile(
        "mma.sync.aligned.m16n8k16.row.col.f32.bf16.bf16.f32 "
        "{%0,%1,%2,%3}, {%4,%5,%6,%7}, {%8,%9}, {%0,%1,%2,%3};"
        : "+f"(c[0]), "+f"(c[1]), "+f"(c[2]), "+f"(c[3])
        : "r"(a[0]), "r"(a[1]), "r"(a[2]), "r"(a[3]), "r"(b[0]), "r"(b[1]));
}
__device__ __forceinline__ void cp16(uint32_t saddr, const void* gaddr) {
    asm volatile("cp.async.cg.shared.global [%0], [%1], 16;" :: "r"(saddr), "l"(gaddr));
}
__device__ __forceinline__ void cp_commit() { asm volatile("cp.async.commit_group;"); }
__device__ __forceinline__ void cp_wait1()  { asm volatile("cp.async.wait_group 1;"); }
// pack {a,b} -> bf16x2 word with a in the LOW half
__device__ __forceinline__ uint32_t bfpack(float a, float b) {
    uint32_t r;
    asm("cvt.rn.bf16x2.f32 %0, %1, %2;" : "=r"(r) : "f"(b), "f"(a));
    return r;
}
__device__ __forceinline__ float bfround(float x) {
    return __bfloat162float(__float2bfloat16_rn(x));
}
__device__ __forceinline__ void cvt2(const float2 q, uint32_t& h, uint32_t& l) {
    h = bfpack(q.x, q.y);
    l = bfpack(q.x - bfround(q.x), q.y - bfround(q.y));
}

// --------------- W preconversion (+ flag counter reset) --------------------
__global__ void wconv_kernel(const float* __restrict__ W) {
    const int i = blockIdx.x * blockDim.x + threadIdx.x;
    if (i == 0) g_nflag = 0;
    if (i < NEXP * HDIM) {
        const float w  = W[i];
        const float hi = bfround(w);
        g_whi[i] = __float2bfloat16_rn(hi);
        g_wlo[i] = __float2bfloat16_rn(w - hi);
    }
}

// ------------------- fused GEMM + softmax + top-k kernel -------------------
// logits[T,64] = X[T,2048].W[64,2048]^T, bf16 hi/lo split (3 HMMA products),
// fp32 accum. 8 warps = 4 K-warpgroups x 2 warps; warp = m32 x n64 (2 mtiles)
// so each B fragment serves 32 tokens (halved smem B traffic vs m16 warps).
// KC=64: one k16 step per warpgroup, 32 chunks -> half the barriers.
// X rides the ring as RAW fp32 (cp.async.cg); A-fragments via ld.shared.v2.f32
// in mma layout + in-register hi/lo convert. W preconverted bf16 via ldmatrix.
// After the mainloop: 2-step smem reduction tree (wg2/3 -> wg0/1 -> wg0),
// then the fused softmax/top-2 epilogue on warps 0-1.
__global__ __launch_bounds__(THREADS, 2)
void router_gemm_kernel(const float* __restrict__ X, float* __restrict__ logits,
                        float* __restrict__ aff, float* __restrict__ idxf) {
    extern __shared__ __align__(16) char smem[];
    const uint32_t sbase = smem_u32(smem);

    const int tid = threadIdx.x, wid = tid >> 5, lane = tid & 31;
    const int m0 = blockIdx.x * BM;

    // cp.async mapping (256 threads, 8x cp16 each):
    //   X: row tid>>2, 64B seg (tid&3) -> 4 cp16
    //   W: row tid>>2, 32B seg (tid&3) for hi and lo -> 2+2 cp16
    const int crow = tid >> 2, cseg = tid & 3;
    const float* gx          = X + (size_t)(m0 + crow) * HDIM + cseg * 16;
    const __nv_bfloat16* gwh = g_whi + (size_t)crow * HDIM + cseg * 16;
    const __nv_bfloat16* gwl = g_wlo + (size_t)crow * HDIM + cseg * 16;
    const uint32_t x_dst = (uint32_t)(crow * XROWB + cseg * 64);
    const uint32_t w_dst = (uint32_t)(crow * WROWB + cseg * 32);

    #define ISSUE_STAGE(sidx, c) do {                                          \
        const uint32_t st_ = sbase + (sidx) * STG_B;                            \
        const int ko = (c) * KC;                                                \
        cp16(st_ + STG_X + x_dst,        gx + ko);                              \
        cp16(st_ + STG_X + x_dst + 16,   gx + ko + 4);                          \
        cp16(st_ + STG_X + x_dst + 32,   gx + ko + 8);                          \
        cp16(st_ + STG_X + x_dst + 48,   gx + ko + 12);                         \
        cp16(st_ + STG_WHI + w_dst,      gwh + ko);                             \
        cp16(st_ + STG_WHI + w_dst + 16, gwh + ko + 8);                         \
        cp16(st_ + STG_WLO + w_dst,      gwl + ko);                             \
        cp16(st_ + STG_WLO + w_dst + 16, gwl + ko + 8);                         \
    } while (0)

    // prologue: chunks 0,1 in flight
    ISSUE_STAGE(0, 0); cp_commit();
    ISSUE_STAGE(1, 1); cp_commit();

    float acc[2][8][4];
    #pragma unroll
    for (int mt = 0; mt < 2; mt++)
        #pragma unroll
        for (int nt = 0; nt < 8; nt++)
            #pragma unroll
            for (int q = 0; q < 4; q++) acc[mt][nt][q] = 0.f;

    // fragment addressing: wg = k16 step (0..3), mhalf = rows mhalf*32..+31
    const int wg = wid >> 1, mhalf = wid & 1;
    const int r = lane >> 2, t = lane & 3;
    const int b_nrow = (lane & 7) + ((lane >> 4) & 1) * 8;
    const int b_kb   = ((lane >> 3) & 1) * 16;
    const uint32_t a_base0 = (uint32_t)((mhalf * 32 + r) * XROWB + wg * 64 + t * 8);
    const uint32_t b_base  = (uint32_t)(wg * 32 + b_kb);

    int stg = 0, stg_i = 2;   // stage of chunk c / chunk c+2
    #pragma unroll 1
    for (int c = 0; c < NCH; c++) {
        cp_wait1();          // chunk c resident (1 younger group pending)
        __syncthreads();     // visibility + all warps done with chunk c-1

        if (c + 2 < NCH) ISSUE_STAGE(stg_i, c + 2);
        cp_commit();         // constant-rate commits (empty at tail)

        const uint32_t st    = sbase + stg * STG_B;
        const uint32_t xs    = st + STG_X;
        const uint32_t whi_b = st + STG_WHI;
        const uint32_t wlo_b = st + STG_WLO;
        if (++stg   == NSTG) stg   = 0;
        if (++stg_i == NSTG) stg_i = 0;

        // A fragments: both mtiles, direct shared loads + in-reg convert
        uint32_t ah[2][4], al[2][4];
        #pragma unroll
        for (int mt = 0; mt < 2; mt++) {
            const uint32_t ab = xs + a_base0 + (uint32_t)(mt * 16 * XROWB);
            const float2 q0 = lds64(ab);
            const float2 q1 = lds64(ab + 8 * XROWB);
            const float2 q2 = lds64(ab + 32);
            const float2 q3 = lds64(ab + 8 * XROWB + 32);
            cvt2(q0, ah[mt][0], al[mt][0]);
            cvt2(q1, ah[mt][1], al[mt][1]);
            cvt2(q2, ah[mt][2], al[mt][2]);
            cvt2(q3, ah[mt][3], al[mt][3]);
        }
        // B fragments in two nt-batches (register cap)
        #pragma unroll
        for (int bb = 0; bb < 2; bb++) {
            uint32_t bh[4][2], bl[4][2];
            #pragma unroll
            for (int p = 0; p < 2; p++) {
                const uint32_t boff = (uint32_t)(((bb * 2 + p) * 16 + b_nrow) * WROWB) + b_base;
                ldsm4(bh[2 * p][0], bh[2 * p][1], bh[2 * p + 1][0], bh[2 * p + 1][1], whi_b + boff);
                ldsm4(bl[2 * p][0], bl[2 * p][1], bl[2 * p + 1][0], bl[2 * p + 1][1], wlo_b + boff);
            }
            #pragma unroll
            for (int mt = 0; mt < 2; mt++)
                #pragma unroll
                for (int n = 0; n < 4; n++) {
                    float* a4 = acc[mt][bb * 4 + n];
                    mma16816(a4, ah[mt], bh[n]);   // hi*hi
                    mma16816(a4, ah[mt], bl[n]);   // hi*lo
                    mma16816(a4, al[mt], bh[n]);   // lo*hi
                }
        }
    }
    #undef ISSUE_STAGE

    // ---- reduction tree across the 4 K-warpgroups (ring smem reused) ------
    // spill layout: float4 at (((sp*2+mt)*8 + nt)*32 + lane)*16
    __syncthreads();
    if (wid >= 4) {          // wg2,3 spill
        const int sp = wid - 4;
        #pragma unroll
        for (int mt = 0; mt < 2; mt++)
            #pragma unroll
            for (int nt = 0; nt < 8; nt++)
                sts128f(sbase + (uint32_t)((((sp * 2 + mt) * 8 + nt) * 32 + lane) * 16),
                        acc[mt][nt][0], acc[mt][nt][1], acc[mt][nt][2], acc[mt][nt][3]);
    }
    __syncthreads();
    if (wid < 4) {           // wg0,1 absorb (warp w <- warp w+4, same mhalf)
        const int sp = wid;
        #pragma unroll
        for (int mt = 0; mt < 2; mt++)
            #pragma unroll
            for (int nt = 0; nt < 8; nt++) {
                const float4 p = lds128f(sbase + (uint32_t)((((sp * 2 + mt) * 8 + nt) * 32 + lane) * 16));
                acc[mt][nt][0] += p.x; acc[mt][nt][1] += p.y;
                acc[mt][nt][2] += p.z; acc[mt][nt][3] += p.w;
            }
    }
    __syncthreads();
    if (wid == 2 || wid == 3) {  // wg1 spills its combined partials
        const int sp = wid - 2;
        #pragma unroll
        for (int mt = 0; mt < 2; mt++)
            #pragma unroll
            for (int nt = 0; nt < 8; nt++)
                sts128f(sbase + (uint32_t)((((sp * 2 + mt) * 8 + nt) * 32 + lane) * 16),
                        acc[mt][nt][0], acc[mt][nt][1], acc[mt][nt][2], acc[mt][nt][3]);
    }
    __syncthreads();
    if (wid >= 2) return;        // warps 0,1 own the final sums + epilogue
    {
        const int sp = wid;
        #pragma unroll
        for (int mt = 0; mt < 2; mt++)
            #pragma unroll
            for (int nt = 0; nt < 8; nt++) {
                const float4 p = lds128f(sbase + (uint32_t)((((sp * 2 + mt) * 8 + nt) * 32 + lane) * 16));
                acc[mt][nt][0] += p.x; acc[mt][nt][1] += p.y;
                acc[mt][nt][2] += p.z; acc[mt][nt][3] += p.w;
            }
    }

    // ---- fused epilogue: warp wid handles rows wid*32 .. +31 --------------
    const int g = r;
    #pragma unroll
    for (int mt = 0; mt < 2; mt++) {
        #pragma unroll
        for (int j = 0; j < 2; j++) {
            const int row = m0 + wid * 32 + mt * 16 + j * 8 + g;
            float v[16];
            #pragma unroll
            for (int nt = 0; nt < 8; nt++) {
                v[2 * nt]     = acc[mt][nt][2 * j];
                v[2 * nt + 1] = acc[mt][nt][2 * j + 1];
            }
            float* lp = logits + (size_t)row * NEXP;
            #pragma unroll
            for (int nt = 0; nt < 8; nt++)
                *(float2*)&lp[nt * 8 + 2 * t] = make_float2(v[2 * nt], v[2 * nt + 1]);

            // local top-3 (ascending col order, strict > -> lowest-index first)
            float b1 = -CUDART_INF_F, b2 = -CUDART_INF_F, b3 = -CUDART_INF_F;
            int i1 = 0, i2 = 0;
            #pragma unroll
            for (int q = 0; q < 16; q++) {
                const int col = (q >> 1) * 8 + 2 * t + (q & 1);
                const float val = v[q];
                if (val > b1)      { b3 = b2; b2 = b1; i2 = i1; b1 = val; i1 = col; }
                else if (val > b2) { b3 = b2; b2 = val; i2 = col; }
                else if (val > b3) { b3 = val; }
            }
            // quad merge (xor 1, then 2); 3rd best is value-only (gap2 test)
            #pragma unroll
            for (int off = 1; off <= 2; off <<= 1) {
                const float ob1 = __shfl_xor_sync(0xffffffffu, b1, off);
                const int   oi1 = __shfl_xor_sync(0xffffffffu, i1, off);
                const float ob2 = __shfl_xor_sync(0xffffffffu, b2, off);
                const int   oi2 = __shfl_xor_sync(0xffffffffu, i2, off);
                const float ob3 = __shfl_xor_sync(0xffffffffu, b3, off);
                const bool afirst = (b1 > ob1) || (b1 == ob1 && i1 < oi1);
                const float w1 = afirst ? b1 : ob1;  const int wi1 = afirst ? i1 : oi1;
                const float a2v = afirst ? b2 : ob2; const int a2i = afirst ? i2 : oi2;
                const float a3v = afirst ? b3 : ob3;
                const float l1v = afirst ? ob1 : b1; const int l1i = afirst ? oi1 : i1;
                const float l2v = afirst ? ob2 : b2;
                const bool sfa = (a2v > l1v) || (a2v == l1v && a2i < l1i);
                b1 = w1; i1 = wi1;
                if (sfa) { b2 = a2v; i2 = a2i; b3 = fmaxf(a3v, l1v); }
                else     { b2 = l1v; i2 = l1i; b3 = fmaxf(a2v, l2v); }
            }

            // softmax (fp32, max-subtracted; deterministic fixed-order sums)
            float s = 0.f;
            #pragma unroll
            for (int q = 0; q < 16; q++) { v[q] = expf(v[q] - b1); s += v[q]; }
            s += __shfl_xor_sync(0xffffffffu, s, 1);
            s += __shfl_xor_sync(0xffffffffu, s, 2);
            const float inv = 1.f / s;
            float* ap = aff + (size_t)row * NEXP;
            #pragma unroll
            for (int nt = 0; nt < 8; nt++)
                *(float2*)&ap[nt * 8 + 2 * t] = make_float2(v[2 * nt] * inv, v[2 * nt + 1] * inv);

            if (t == 0) {
                idxf[2 * (size_t)row + 0] = (float)i1;
                idxf[2 * (size_t)row + 1] = (float)i2;
                if (b1 - b2 < TAU || b2 - b3 < TAU)
                    g_ftok[atomicAdd(&g_nflag, 1)] = row;
            }
        }
    }
}

// ---------------- exact fp32 top-2 for ambiguous tokens --------------------
__global__ __launch_bounds__(256)
void refine_kernel(const float* __restrict__ X, const float* __restrict__ W,
                   float* __restrict__ idxf) {
    __shared__ float sl[NEXP];
    const int lane = threadIdx.x & 31, w = threadIdx.x >> 5;
    const int n = g_nflag;

    for (int tix = blockIdx.x; tix < n; tix += gridDim.x) {
        const int tok = g_ftok[tix];
        const float4* xp = (const float4*)(X + (size_t)tok * HDIM);
        float acc[8];
        #pragma unroll
        for (int e = 0; e < 8; e++) acc[e] = 0.f;

        #pragma unroll 4
        for (int k = lane; k < HDIM / 4; k += 32) {
            const float4 x = xp[k];
            #pragma unroll
            for (int e = 0; e < 8; e++) {
                const float4 b = ((const float4*)(W + (size_t)(w * 8 + e) * HDIM))[k];
                acc[e] = fmaf(x.x, b.x, fmaf(x.y, b.y, fmaf(x.z, b.z, fmaf(x.w, b.w, acc[e]))));
            }
        }
        #pragma unroll
        for (int e = 0; e < 8; e++) {
            float s = acc[e];
            #pragma unroll
            for (int off = 16; off; off >>= 1) s += __shfl_xor_sync(0xffffffffu, s, off);
            if (lane == 0) sl[w * 8 + e] = s;
        }
        __syncthreads();
        if (threadIdx.x == 0) {
            float b1 = -CUDART_INF_F, b2 = -CUDART_INF_F;
            int i1 = 0, i2 = 0;
            for (int e = 0; e < NEXP; e++) {
                const float vv = sl[e];
                if (vv > b1)      { b2 = b1; i2 = i1; b1 = vv; i1 = e; }
                else if (vv > b2) { b2 = vv; i2 = e; }
            }
            idxf[2 * (size_t)tok + 0] = (float)i1;
            idxf[2 * (size_t)tok + 1] = (float)i2;
        }
        __syncthreads();
    }
}

// ---------------------------------------------------------------------------
// d_out (fp32): [0,T*E) logits | [T*E,2TE) affinities | [2TE, 2TE+2T) indices
// ---------------------------------------------------------------------------
extern "C" void kernel_launch(void* const* d_in, const int* in_sizes, int n_in,
                              void* d_out, int out_size) {
    (void)in_sizes; (void)n_in; (void)out_size;
    const float* X = (const float*)d_in[0];
    const float* W = (const float*)d_in[1];
    float* out    = (float*)d_out;
    float* logits = out;
    float* aff    = out + (size_t)NTOK * NEXP;
    float* idxf   = out + 2 * (size_t)NTOK * NEXP;

    cudaFuncSetAttribute(router_gemm_kernel,
                         cudaFuncAttributeMaxDynamicSharedMemorySize, SM_TOTAL);

    wconv_kernel<<<(NEXP * HDIM + 255) / 256, 256>>>(W);
    router_gemm_kernel<<<NTOK / BM, THREADS, SM_TOTAL>>>(X, logits, aff, idxf);
    refine_kernel<<<512, 256>>>(X, W, idxf);
}